// round 3
// baseline (speedup 1.0000x reference)
#include <cuda_runtime.h>
#include <math.h>

typedef unsigned long long u64;

// ---------------------------------------------------------------------------
// Scratch: com = x @ W^T + b   (1024 x 512 fp32)  -- __device__ global (no alloc)
// ---------------------------------------------------------------------------
__device__ float g_com[1024 * 512];

// ---------------------------------------------------------------------------
// Packed fp32x2 helpers (FFMA2 is PTX-only per SASS quickref)
// ---------------------------------------------------------------------------
__device__ __forceinline__ u64 pk2(float lo, float hi) {
    u64 d; asm("mov.b64 %0, {%1, %2};" : "=l"(d) : "f"(lo), "f"(hi)); return d;
}
__device__ __forceinline__ u64 fma2(u64 a, u64 b, u64 c) {
    u64 d; asm("fma.rn.f32x2 %0, %1, %2, %3;" : "=l"(d) : "l"(a), "l"(b), "l"(c)); return d;
}
__device__ __forceinline__ void unpk2(float& lo, float& hi, u64 d) {
    asm("mov.b64 {%0, %1}, %2;" : "=f"(lo), "=f"(hi) : "l"(d));
}

// ---------------------------------------------------------------------------
// GEMM: C[m,n] = sum_k A[m,k] * W[n,k] + bias[n]
// M=1024, N=512, K=2048. BM=BN=64, BK=16, 256 threads, 4x4 per thread (n packed f32x2).
// ---------------------------------------------------------------------------
#define BM 64
#define BN 64
#define BK 16

__global__ __launch_bounds__(256)
void gemm_xwt_kernel(const float* __restrict__ A, const float* __restrict__ Wm,
                     const float* __restrict__ bias, float* __restrict__ C)
{
    __shared__ __align__(16) float As[BK][BM + 4];
    __shared__ __align__(16) float Ws[BK][BN + 4];

    const int tid = threadIdx.x;
    const int m0 = blockIdx.y * BM;
    const int n0 = blockIdx.x * BN;
    const int row = tid >> 2;           // 0..63
    const int kq  = (tid & 3) << 2;     // 0,4,8,12
    const int ty  = tid >> 4;           // 0..15
    const int tx  = tid & 15;           // 0..15

    u64 acc[4][2];
    #pragma unroll
    for (int i = 0; i < 4; ++i)
        #pragma unroll
        for (int j = 0; j < 2; ++j) acc[i][j] = pk2(0.f, 0.f);

    for (int k0 = 0; k0 < 2048; k0 += BK) {
        float4 a4 = *(const float4*)(A  + (size_t)(m0 + row) * 2048 + k0 + kq);
        float4 w4 = *(const float4*)(Wm + (size_t)(n0 + row) * 2048 + k0 + kq);
        __syncthreads();   // previous compute done before overwrite
        As[kq + 0][row] = a4.x; As[kq + 1][row] = a4.y;
        As[kq + 2][row] = a4.z; As[kq + 3][row] = a4.w;
        Ws[kq + 0][row] = w4.x; Ws[kq + 1][row] = w4.y;
        Ws[kq + 2][row] = w4.z; Ws[kq + 3][row] = w4.w;
        __syncthreads();

        #pragma unroll
        for (int kk = 0; kk < BK; ++kk) {
            float4 av = *(const float4*)&As[kk][ty << 2];
            ulonglong2 bv = *(const ulonglong2*)&Ws[kk][tx << 2];
            u64 br0 = bv.x, br1 = bv.y;
            u64 ap;
            ap = pk2(av.x, av.x); acc[0][0] = fma2(ap, br0, acc[0][0]); acc[0][1] = fma2(ap, br1, acc[0][1]);
            ap = pk2(av.y, av.y); acc[1][0] = fma2(ap, br0, acc[1][0]); acc[1][1] = fma2(ap, br1, acc[1][1]);
            ap = pk2(av.z, av.z); acc[2][0] = fma2(ap, br0, acc[2][0]); acc[2][1] = fma2(ap, br1, acc[2][1]);
            ap = pk2(av.w, av.w); acc[3][0] = fma2(ap, br0, acc[3][0]); acc[3][1] = fma2(ap, br1, acc[3][1]);
        }
    }

    #pragma unroll
    for (int i = 0; i < 4; ++i) {
        int mrow = m0 + (ty << 2) + i;
        #pragma unroll
        for (int j = 0; j < 2; ++j) {
            float lo, hi; unpk2(lo, hi, acc[i][j]);
            int n = n0 + (tx << 2) + (j << 1);
            C[(size_t)mrow * 512 + n]     = lo + bias[n];
            C[(size_t)mrow * 512 + n + 1] = hi + bias[n + 1];
        }
    }
}

// ---------------------------------------------------------------------------
// Quantum circuit: 1 CTA per batch row, full state (4096 complex) in SMEM.
// Wire w <-> bit (11 - w).  SMEM index swizzle: a(i) = i ^ ((i>>4) & 0xF)
// (makes all 3 nibble-tile access patterns bank-conflict-free).
// ---------------------------------------------------------------------------
__device__ __forceinline__ int swz(int i) { return i ^ ((i >> 4) & 0xF); }

__device__ __forceinline__ void cgate(float2& a, float2& b,
                                      float2 u00, float2 u01, float2 u10, float2 u11)
{
    float nax = u00.x*a.x - u00.y*a.y + u01.x*b.x - u01.y*b.y;
    float nay = u00.x*a.y + u00.y*a.x + u01.x*b.y + u01.y*b.x;
    float nbx = u10.x*a.x - u10.y*a.y + u11.x*b.x - u11.y*b.y;
    float nby = u10.x*a.y + u10.y*a.x + u11.x*b.y + u11.y*b.x;
    a = make_float2(nax, nay); b = make_float2(nbx, nby);
}

template<int LB>
__device__ __forceinline__ void apply_rot(float2* v, const float2* m)
{
    float2 u00 = m[0], u01 = m[1], u10 = m[2], u11 = m[3];
    #pragma unroll
    for (int p = 0; p < 8; ++p) {
        int k0 = ((p >> LB) << (LB + 1)) | (p & ((1 << LB) - 1));
        cgate(v[k0], v[k0 | (1 << LB)], u00, u01, u10, u11);
    }
}

template<int LB>
__device__ __forceinline__ void apply_h(float2* v)
{
    const float r = 0.70710678118654752f;
    #pragma unroll
    for (int p = 0; p < 8; ++p) {
        int k0 = ((p >> LB) << (LB + 1)) | (p & ((1 << LB) - 1));
        int k1 = k0 | (1 << LB);
        float2 a = v[k0], b = v[k1];
        v[k0] = make_float2((a.x + b.x) * r, (a.y + b.y) * r);
        v[k1] = make_float2((a.x - b.x) * r, (a.y - b.y) * r);
    }
}

// Net gather index of the 12-CNOT chain with range R:
// post-CNOT state s'[i] = s[G(i)],  G = g_0 ∘ g_1 ∘ ... ∘ g_11 (g_11 innermost).
// g_w(i) = i ^ (bit(11-w) of i) << (11 - (w+R)%12).  Linear over GF(2).
template<int R>
__device__ __forceinline__ int cnotG(int i)
{
    #pragma unroll
    for (int w = 11; w >= 0; --w) {
        int pc = 11 - w;
        int pt = 11 - ((w + R) % 12);
        i ^= ((i >> pc) & 1) << pt;
    }
    return i;
}

__global__ __launch_bounds__(256, 2)
void circuit_kernel(const float* __restrict__ x,    // (1024, 2048) img angles
                    const float* __restrict__ qp,   // (2, 12, 3)
                    float* __restrict__ out)        // (1024,)
{
    __shared__ float2 st[4096];          // 32 KB state
    __shared__ float2 rotm[2][12][4];    // Rot matrices
    __shared__ float  red[8];

    const int t = threadIdx.x;
    const int b = blockIdx.x;
    const float* com = g_com + (size_t)b * 512;
    const float* img = x     + (size_t)b * 2048;

    // --- Rot matrices: Rot = RZ(omega) RY(theta) RZ(phi) ---
    if (t < 24) {
        int l = t / 12, w = t % 12;
        float phi = qp[(l * 12 + w) * 3 + 0];
        float th  = qp[(l * 12 + w) * 3 + 1];
        float om  = qp[(l * 12 + w) * 3 + 2];
        float sh, ch;  sincosf(0.5f * th, &sh, &ch);
        float sa, ca;  sincosf(0.5f * (phi + om), &sa, &ca);
        float sb, cb;  sincosf(0.5f * (phi - om), &sb, &cb);
        rotm[l][w][0] = make_float2( ch * ca, -ch * sa);  // m00 = e^{-i(phi+om)/2} c
        rotm[l][w][1] = make_float2(-sh * cb, -sh * sb);  // m01 = -e^{+i(phi-om)/2} s
        rotm[l][w][2] = make_float2( sh * cb, -sh * sb);  // m10 = e^{-i(phi-om)/2} s
        rotm[l][w][3] = make_float2( ch * ca,  ch * sa);  // m11 = e^{+i(phi+om)/2} c
    }
    __syncthreads();

    float2 v[16];

    // ===== Pass 1 (nibble A: bits 0-3 local, i = t*16 + k) =====
    // Generate post-FRQI(com) state analytically, then layer-0 Rots on wires 11,10,9,8.
    #pragma unroll
    for (int k = 0; k < 16; ++k) {
        int i = (t << 4) | k;
        if (i & 3) {                          // wires 10,11 must be |0>
            v[k] = make_float2(0.f, 0.f);
        } else {
            int j = (i >> 2) & 511;           // wires 1..9 (wire1 = MSB)
            int aidx = __brev((unsigned)j) >> 23;   // 9-bit reversal
            float sn, cs; sincosf(0.5f * com[aidx], &sn, &cs);
            float amp = ((i >> 11) & 1) ? sn : cs;
            v[k] = make_float2(amp * 0.04419417382415922f, 0.f);  // 1/sqrt(512)
        }
    }
    apply_rot<0>(v, rotm[0][11]); apply_rot<1>(v, rotm[0][10]);
    apply_rot<2>(v, rotm[0][9]);  apply_rot<3>(v, rotm[0][8]);
    #pragma unroll
    for (int k = 0; k < 16; ++k) st[swz((t << 4) | k)] = v[k];
    __syncthreads();

    // ===== Pass 2 (nibble B: bits 4-7 local) : layer-0 Rots wires 7,6,5,4 =====
    #pragma unroll
    for (int k = 0; k < 16; ++k) v[k] = st[swz(((t >> 4) << 8) | (k << 4) | (t & 15))];
    apply_rot<0>(v, rotm[0][7]); apply_rot<1>(v, rotm[0][6]);
    apply_rot<2>(v, rotm[0][5]); apply_rot<3>(v, rotm[0][4]);
    #pragma unroll
    for (int k = 0; k < 16; ++k) st[swz(((t >> 4) << 8) | (k << 4) | (t & 15))] = v[k];
    __syncthreads();

    // ===== Pass 3 (nibble C: bits 8-11 local) : layer-0 Rots wires 3,2,1,0 =====
    #pragma unroll
    for (int k = 0; k < 16; ++k) v[k] = st[swz((k << 8) | t)];
    apply_rot<0>(v, rotm[0][3]); apply_rot<1>(v, rotm[0][2]);
    apply_rot<2>(v, rotm[0][1]); apply_rot<3>(v, rotm[0][0]);
    #pragma unroll
    for (int k = 0; k < 16; ++k) st[swz((k << 8) | t)] = v[k];
    __syncthreads();

    // ===== Pass 4 (A) : CNOT chain r=1 folded into gather, layer-1 Rots 11..8 =====
    {
        int base = cnotG<1>(t << 4);
        int m0 = cnotG<1>(1), m1 = cnotG<1>(2), m2 = cnotG<1>(4), m3 = cnotG<1>(8);
        #pragma unroll
        for (int k = 0; k < 16; ++k) {
            int gi = base ^ ((k & 1) ? m0 : 0) ^ ((k & 2) ? m1 : 0)
                          ^ ((k & 4) ? m2 : 0) ^ ((k & 8) ? m3 : 0);
            v[k] = st[swz(gi)];
        }
    }
    __syncthreads();   // all gathered reads done before in-place writes
    apply_rot<0>(v, rotm[1][11]); apply_rot<1>(v, rotm[1][10]);
    apply_rot<2>(v, rotm[1][9]);  apply_rot<3>(v, rotm[1][8]);
    #pragma unroll
    for (int k = 0; k < 16; ++k) st[swz((t << 4) | k)] = v[k];
    __syncthreads();

    // ===== Pass 5 (B) : layer-1 Rots wires 7..4 =====
    #pragma unroll
    for (int k = 0; k < 16; ++k) v[k] = st[swz(((t >> 4) << 8) | (k << 4) | (t & 15))];
    apply_rot<0>(v, rotm[1][7]); apply_rot<1>(v, rotm[1][6]);
    apply_rot<2>(v, rotm[1][5]); apply_rot<3>(v, rotm[1][4]);
    #pragma unroll
    for (int k = 0; k < 16; ++k) st[swz(((t >> 4) << 8) | (k << 4) | (t & 15))] = v[k];
    __syncthreads();

    // ===== Pass 6 (C) : layer-1 Rots wires 3..0 =====
    #pragma unroll
    for (int k = 0; k < 16; ++k) v[k] = st[swz((k << 8) | t)];
    apply_rot<0>(v, rotm[1][3]); apply_rot<1>(v, rotm[1][2]);
    apply_rot<2>(v, rotm[1][1]); apply_rot<3>(v, rotm[1][0]);
    #pragma unroll
    for (int k = 0; k < 16; ++k) st[swz((k << 8) | t)] = v[k];
    __syncthreads();

    // ===== Pass 7 (A) : CNOT chain r=2 folded into gather, H on bits 0-3 =====
    {
        int base = cnotG<2>(t << 4);
        int m0 = cnotG<2>(1), m1 = cnotG<2>(2), m2 = cnotG<2>(4), m3 = cnotG<2>(8);
        #pragma unroll
        for (int k = 0; k < 16; ++k) {
            int gi = base ^ ((k & 1) ? m0 : 0) ^ ((k & 2) ? m1 : 0)
                          ^ ((k & 4) ? m2 : 0) ^ ((k & 8) ? m3 : 0);
            v[k] = st[swz(gi)];
        }
    }
    __syncthreads();
    apply_h<0>(v); apply_h<1>(v); apply_h<2>(v); apply_h<3>(v);
    #pragma unroll
    for (int k = 0; k < 16; ++k) st[swz((t << 4) | k)] = v[k];
    __syncthreads();

    // ===== Pass 8 (B) : H on bits 4-7 =====
    #pragma unroll
    for (int k = 0; k < 16; ++k) v[k] = st[swz(((t >> 4) << 8) | (k << 4) | (t & 15))];
    apply_h<0>(v); apply_h<1>(v); apply_h<2>(v); apply_h<3>(v);
    #pragma unroll
    for (int k = 0; k < 16; ++k) st[swz(((t >> 4) << 8) | (k << 4) | (t & 15))] = v[k];
    __syncthreads();

    // ===== Pass 9 (C) : H on bits 8,9,10 (wires 3,2,1), UC-RY on wire 0, measure =====
    #pragma unroll
    for (int k = 0; k < 16; ++k) v[k] = st[swz((k << 8) | t)];
    apply_h<0>(v); apply_h<1>(v); apply_h<2>(v);

    #pragma unroll
    for (int k0 = 0; k0 < 8; ++k0) {
        int i0 = (k0 << 8) | t;                          // bit 11 = 0
        int aidx = __brev((unsigned)i0) >> 21;           // 11-bit reversal
        float sn, cs; sincosf(0.5f * img[aidx], &sn, &cs);
        float2 a = v[k0], bb = v[k0 + 8];
        v[k0]     = make_float2(cs * a.x - sn * bb.x, cs * a.y - sn * bb.y);
        v[k0 + 8] = make_float2(sn * a.x + cs * bb.x, sn * a.y + cs * bb.y);
    }

    float acc = 0.f;
    #pragma unroll
    for (int k = 0; k < 8; ++k)  acc -= v[k].x * v[k].x + v[k].y * v[k].y;
    #pragma unroll
    for (int k = 8; k < 16; ++k) acc += v[k].x * v[k].x + v[k].y * v[k].y;

    #pragma unroll
    for (int o = 16; o; o >>= 1) acc += __shfl_xor_sync(0xffffffffu, acc, o);
    if ((t & 31) == 0) red[t >> 5] = acc;
    __syncthreads();
    if (t == 0) {
        float s = 0.f;
        #pragma unroll
        for (int w = 0; w < 8; ++w) s += red[w];
        out[b] = s;
    }
}

// ---------------------------------------------------------------------------
extern "C" void kernel_launch(void* const* d_in, const int* in_sizes, int n_in,
                              void* d_out, int out_size)
{
    const float* x  = (const float*)d_in[0];   // (1024, 2, 32, 32) -> (1024, 2048)
    const float* Wm = (const float*)d_in[1];   // (512, 2048)
    const float* bb = (const float*)d_in[2];   // (512,)
    const float* qp = (const float*)d_in[3];   // (2, 12, 3)
    float* out = (float*)d_out;                // (1024,)

    float* com;
    cudaGetSymbolAddress((void**)&com, g_com);

    dim3 gemm_grid(512 / BN, 1024 / BM);
    gemm_xwt_kernel<<<gemm_grid, 256>>>(x, Wm, bb, com);
    circuit_kernel<<<1024, 256>>>(x, qp, out);
}

// round 4
// speedup vs baseline: 1.4330x; 1.4330x over previous
#include <cuda_runtime.h>
#include <math.h>

typedef unsigned long long u64;

#define SPLITK 4

// Split-K partial sums of x @ W^T (bias added in circuit kernel). No allocs.
__device__ float g_com4[SPLITK][1024 * 512];

// ---------------------------------------------------------------------------
// Packed fp32x2 helpers (FFMA2 is PTX-only)
// ---------------------------------------------------------------------------
__device__ __forceinline__ u64 pk2(float lo, float hi) {
    u64 d; asm("mov.b64 %0, {%1, %2};" : "=l"(d) : "f"(lo), "f"(hi)); return d;
}
__device__ __forceinline__ u64 fma2(u64 a, u64 b, u64 c) {
    u64 d; asm("fma.rn.f32x2 %0, %1, %2, %3;" : "=l"(d) : "l"(a), "l"(b), "l"(c)); return d;
}

// ---------------------------------------------------------------------------
// GEMM v2: C[sk][m,n] partial = sum_{k in sk-slice} A[m,k] * W[n,k]
// M=1024, N=512, K=2048, SPLITK=4 (512 K per CTA).
// BM=BN=128, BK=16, 256 threads, 8x8 per thread, f32x2 accumulators.
// Register prefetch (distance 1) + SMEM double buffer, ONE sync per iter.
// ---------------------------------------------------------------------------
__global__ __launch_bounds__(256)
void gemm_v2(const float* __restrict__ A, const float* __restrict__ Wm)
{
    __shared__ __align__(16) float As[2][16][132];
    __shared__ __align__(16) float Ws[2][16][132];

    const int tid = threadIdx.x;
    const int n0 = blockIdx.x * 128;
    const int m0 = blockIdx.y * 128;
    const int kb = blockIdx.z * 512;
    const int r  = tid >> 1;          // 0..127 (row of A / row of W tile)
    const int kh = (tid & 1) << 3;    // 0 or 8
    const int ty = tid >> 4;          // 0..15
    const int tx = tid & 15;          // 0..15

    const float* Ap = A  + (size_t)(m0 + r) * 2048 + kb + kh;
    const float* Wp = Wm + (size_t)(n0 + r) * 2048 + kb + kh;

    u64 acc[8][4];
    #pragma unroll
    for (int i = 0; i < 8; ++i)
        #pragma unroll
        for (int j = 0; j < 4; ++j) acc[i][j] = 0ull;

    // prefetch iter 0
    float4 a0 = *(const float4*)Ap;
    float4 a1 = *(const float4*)(Ap + 4);
    float4 w0 = *(const float4*)Wp;
    float4 w1 = *(const float4*)(Wp + 4);

    #pragma unroll 1
    for (int it = 0; it < 32; ++it) {
        const int buf = it & 1;
        // store current iter's data (k-transposed)
        As[buf][kh + 0][r] = a0.x; As[buf][kh + 1][r] = a0.y;
        As[buf][kh + 2][r] = a0.z; As[buf][kh + 3][r] = a0.w;
        As[buf][kh + 4][r] = a1.x; As[buf][kh + 5][r] = a1.y;
        As[buf][kh + 6][r] = a1.z; As[buf][kh + 7][r] = a1.w;
        Ws[buf][kh + 0][r] = w0.x; Ws[buf][kh + 1][r] = w0.y;
        Ws[buf][kh + 2][r] = w0.z; Ws[buf][kh + 3][r] = w0.w;
        Ws[buf][kh + 4][r] = w1.x; Ws[buf][kh + 5][r] = w1.y;
        Ws[buf][kh + 6][r] = w1.z; Ws[buf][kh + 7][r] = w1.w;

        // prefetch next iter into registers (hidden behind compute below)
        if (it + 1 < 32) {
            const float* Ap2 = Ap + (it + 1) * 16;
            const float* Wp2 = Wp + (it + 1) * 16;
            a0 = *(const float4*)Ap2; a1 = *(const float4*)(Ap2 + 4);
            w0 = *(const float4*)Wp2; w1 = *(const float4*)(Wp2 + 4);
        }
        __syncthreads();

        #pragma unroll
        for (int kk = 0; kk < 16; ++kk) {
            float4 af0 = *(const float4*)&As[buf][kk][ty << 3];
            float4 af1 = *(const float4*)&As[buf][kk][(ty << 3) + 4];
            ulonglong2 q0 = *(const ulonglong2*)&Ws[buf][kk][tx << 2];
            ulonglong2 q1 = *(const ulonglong2*)&Ws[buf][kk][64 + (tx << 2)];
            float av[8] = {af0.x, af0.y, af0.z, af0.w, af1.x, af1.y, af1.z, af1.w};
            #pragma unroll
            for (int i = 0; i < 8; ++i) {
                u64 ap = pk2(av[i], av[i]);
                acc[i][0] = fma2(ap, q0.x, acc[i][0]);
                acc[i][1] = fma2(ap, q0.y, acc[i][1]);
                acc[i][2] = fma2(ap, q1.x, acc[i][2]);
                acc[i][3] = fma2(ap, q1.y, acc[i][3]);
            }
        }
        // no bottom sync: next iter's STS targets the other buffer.
    }

    float* Cp = g_com4[blockIdx.z];
    #pragma unroll
    for (int i = 0; i < 8; ++i) {
        int row = m0 + (ty << 3) + i;
        *(ulonglong2*)&Cp[(size_t)row * 512 + n0 + (tx << 2)] =
            make_ulonglong2(acc[i][0], acc[i][1]);
        *(ulonglong2*)&Cp[(size_t)row * 512 + n0 + 64 + (tx << 2)] =
            make_ulonglong2(acc[i][2], acc[i][3]);
    }
}

// ---------------------------------------------------------------------------
// Quantum circuit: 1 CTA per batch row, full state (4096 complex) in SMEM.
// Wire w <-> bit (11 - w).  SMEM index swizzle: a(i) = i ^ ((i>>4) & 0xF)
// ---------------------------------------------------------------------------
__device__ __forceinline__ int swz(int i) { return i ^ ((i >> 4) & 0xF); }

__device__ __forceinline__ void cgate(float2& a, float2& b,
                                      float2 u00, float2 u01, float2 u10, float2 u11)
{
    float nax = u00.x*a.x - u00.y*a.y + u01.x*b.x - u01.y*b.y;
    float nay = u00.x*a.y + u00.y*a.x + u01.x*b.y + u01.y*b.x;
    float nbx = u10.x*a.x - u10.y*a.y + u11.x*b.x - u11.y*b.y;
    float nby = u10.x*a.y + u10.y*a.x + u11.x*b.y + u11.y*b.x;
    a = make_float2(nax, nay); b = make_float2(nbx, nby);
}

template<int LB>
__device__ __forceinline__ void apply_rot(float2* v, const float2* m)
{
    float2 u00 = m[0], u01 = m[1], u10 = m[2], u11 = m[3];
    #pragma unroll
    for (int p = 0; p < 8; ++p) {
        int k0 = ((p >> LB) << (LB + 1)) | (p & ((1 << LB) - 1));
        cgate(v[k0], v[k0 | (1 << LB)], u00, u01, u10, u11);
    }
}

template<int LB>
__device__ __forceinline__ void apply_h(float2* v)
{
    const float r = 0.70710678118654752f;
    #pragma unroll
    for (int p = 0; p < 8; ++p) {
        int k0 = ((p >> LB) << (LB + 1)) | (p & ((1 << LB) - 1));
        int k1 = k0 | (1 << LB);
        float2 a = v[k0], b = v[k1];
        v[k0] = make_float2((a.x + b.x) * r, (a.y + b.y) * r);
        v[k1] = make_float2((a.x - b.x) * r, (a.y - b.y) * r);
    }
}

// Net gather index of the 12-CNOT chain with range R (GF(2)-linear).
template<int R>
__device__ __forceinline__ int cnotG(int i)
{
    #pragma unroll
    for (int w = 11; w >= 0; --w) {
        int pc = 11 - w;
        int pt = 11 - ((w + R) % 12);
        i ^= ((i >> pc) & 1) << pt;
    }
    return i;
}

__global__ __launch_bounds__(256, 2)
void circuit_kernel(const float* __restrict__ x,    // (1024, 2048) img angles
                    const float* __restrict__ bias, // (512,)
                    const float* __restrict__ qp,   // (2, 12, 3)
                    float* __restrict__ out)        // (1024,)
{
    __shared__ float2 st[4096];          // 32 KB state
    __shared__ float2 rotm[2][12][4];    // Rot matrices
    __shared__ float  red[8];

    const int t = threadIdx.x;
    const int b = blockIdx.x;
    const float* img = x + (size_t)b * 2048;
    const size_t crow = (size_t)b * 512;

    // --- Rot matrices: Rot = RZ(omega) RY(theta) RZ(phi) ---
    if (t < 24) {
        int l = t / 12, w = t % 12;
        float phi = qp[(l * 12 + w) * 3 + 0];
        float th  = qp[(l * 12 + w) * 3 + 1];
        float om  = qp[(l * 12 + w) * 3 + 2];
        float sh, ch;  sincosf(0.5f * th, &sh, &ch);
        float sa, ca;  sincosf(0.5f * (phi + om), &sa, &ca);
        float sb, cb;  sincosf(0.5f * (phi - om), &sb, &cb);
        rotm[l][w][0] = make_float2( ch * ca, -ch * sa);
        rotm[l][w][1] = make_float2(-sh * cb, -sh * sb);
        rotm[l][w][2] = make_float2( sh * cb, -sh * sb);
        rotm[l][w][3] = make_float2( ch * ca,  ch * sa);
    }
    __syncthreads();

    float2 v[16];

    // ===== Pass 1 (nibble A) : analytic post-FRQI(com) state, layer-0 Rots 11..8 =====
    #pragma unroll
    for (int k = 0; k < 16; ++k) {
        int i = (t << 4) | k;
        if (i & 3) {
            v[k] = make_float2(0.f, 0.f);
        } else {
            int j = (i >> 2) & 511;
            int aidx = __brev((unsigned)j) >> 23;
            float comv = bias[aidx]
                       + g_com4[0][crow + aidx] + g_com4[1][crow + aidx]
                       + g_com4[2][crow + aidx] + g_com4[3][crow + aidx];
            float sn, cs; sincosf(0.5f * comv, &sn, &cs);
            float amp = ((i >> 11) & 1) ? sn : cs;
            v[k] = make_float2(amp * 0.04419417382415922f, 0.f);  // 1/sqrt(512)
        }
    }
    apply_rot<0>(v, rotm[0][11]); apply_rot<1>(v, rotm[0][10]);
    apply_rot<2>(v, rotm[0][9]);  apply_rot<3>(v, rotm[0][8]);
    #pragma unroll
    for (int k = 0; k < 16; ++k) st[swz((t << 4) | k)] = v[k];
    __syncthreads();

    // ===== Pass 2 (B) : layer-0 Rots 7..4 =====
    #pragma unroll
    for (int k = 0; k < 16; ++k) v[k] = st[swz(((t >> 4) << 8) | (k << 4) | (t & 15))];
    apply_rot<0>(v, rotm[0][7]); apply_rot<1>(v, rotm[0][6]);
    apply_rot<2>(v, rotm[0][5]); apply_rot<3>(v, rotm[0][4]);
    #pragma unroll
    for (int k = 0; k < 16; ++k) st[swz(((t >> 4) << 8) | (k << 4) | (t & 15))] = v[k];
    __syncthreads();

    // ===== Pass 3 (C) : layer-0 Rots 3..0 =====
    #pragma unroll
    for (int k = 0; k < 16; ++k) v[k] = st[swz((k << 8) | t)];
    apply_rot<0>(v, rotm[0][3]); apply_rot<1>(v, rotm[0][2]);
    apply_rot<2>(v, rotm[0][1]); apply_rot<3>(v, rotm[0][0]);
    #pragma unroll
    for (int k = 0; k < 16; ++k) st[swz((k << 8) | t)] = v[k];
    __syncthreads();

    // ===== Pass 4 (A) : CNOT r=1 folded gather, layer-1 Rots 11..8 =====
    {
        int base = cnotG<1>(t << 4);
        int m0 = cnotG<1>(1), m1 = cnotG<1>(2), m2 = cnotG<1>(4), m3 = cnotG<1>(8);
        #pragma unroll
        for (int k = 0; k < 16; ++k) {
            int gi = base ^ ((k & 1) ? m0 : 0) ^ ((k & 2) ? m1 : 0)
                          ^ ((k & 4) ? m2 : 0) ^ ((k & 8) ? m3 : 0);
            v[k] = st[swz(gi)];
        }
    }
    __syncthreads();
    apply_rot<0>(v, rotm[1][11]); apply_rot<1>(v, rotm[1][10]);
    apply_rot<2>(v, rotm[1][9]);  apply_rot<3>(v, rotm[1][8]);
    #pragma unroll
    for (int k = 0; k < 16; ++k) st[swz((t << 4) | k)] = v[k];
    __syncthreads();

    // ===== Pass 5 (B) : layer-1 Rots 7..4 =====
    #pragma unroll
    for (int k = 0; k < 16; ++k) v[k] = st[swz(((t >> 4) << 8) | (k << 4) | (t & 15))];
    apply_rot<0>(v, rotm[1][7]); apply_rot<1>(v, rotm[1][6]);
    apply_rot<2>(v, rotm[1][5]); apply_rot<3>(v, rotm[1][4]);
    #pragma unroll
    for (int k = 0; k < 16; ++k) st[swz(((t >> 4) << 8) | (k << 4) | (t & 15))] = v[k];
    __syncthreads();

    // ===== Pass 6 (C) : layer-1 Rots 3..0 =====
    #pragma unroll
    for (int k = 0; k < 16; ++k) v[k] = st[swz((k << 8) | t)];
    apply_rot<0>(v, rotm[1][3]); apply_rot<1>(v, rotm[1][2]);
    apply_rot<2>(v, rotm[1][1]); apply_rot<3>(v, rotm[1][0]);
    #pragma unroll
    for (int k = 0; k < 16; ++k) st[swz((k << 8) | t)] = v[k];
    __syncthreads();

    // ===== Pass 7 (A) : CNOT r=2 folded gather, H on bits 0-3 =====
    {
        int base = cnotG<2>(t << 4);
        int m0 = cnotG<2>(1), m1 = cnotG<2>(2), m2 = cnotG<2>(4), m3 = cnotG<2>(8);
        #pragma unroll
        for (int k = 0; k < 16; ++k) {
            int gi = base ^ ((k & 1) ? m0 : 0) ^ ((k & 2) ? m1 : 0)
                          ^ ((k & 4) ? m2 : 0) ^ ((k & 8) ? m3 : 0);
            v[k] = st[swz(gi)];
        }
    }
    __syncthreads();
    apply_h<0>(v); apply_h<1>(v); apply_h<2>(v); apply_h<3>(v);
    #pragma unroll
    for (int k = 0; k < 16; ++k) st[swz((t << 4) | k)] = v[k];
    __syncthreads();

    // ===== Pass 8 (B) : H on bits 4-7 =====
    #pragma unroll
    for (int k = 0; k < 16; ++k) v[k] = st[swz(((t >> 4) << 8) | (k << 4) | (t & 15))];
    apply_h<0>(v); apply_h<1>(v); apply_h<2>(v); apply_h<3>(v);
    #pragma unroll
    for (int k = 0; k < 16; ++k) st[swz(((t >> 4) << 8) | (k << 4) | (t & 15))] = v[k];
    __syncthreads();

    // ===== Pass 9 (C) : H bits 8-10, UC-RY(img) on wire 0, measure =====
    #pragma unroll
    for (int k = 0; k < 16; ++k) v[k] = st[swz((k << 8) | t)];
    apply_h<0>(v); apply_h<1>(v); apply_h<2>(v);

    #pragma unroll
    for (int k0 = 0; k0 < 8; ++k0) {
        int i0 = (k0 << 8) | t;
        int aidx = __brev((unsigned)i0) >> 21;
        float sn, cs; sincosf(0.5f * img[aidx], &sn, &cs);
        float2 a = v[k0], bb = v[k0 + 8];
        v[k0]     = make_float2(cs * a.x - sn * bb.x, cs * a.y - sn * bb.y);
        v[k0 + 8] = make_float2(sn * a.x + cs * bb.x, sn * a.y + cs * bb.y);
    }

    float acc = 0.f;
    #pragma unroll
    for (int k = 0; k < 8; ++k)  acc -= v[k].x * v[k].x + v[k].y * v[k].y;
    #pragma unroll
    for (int k = 8; k < 16; ++k) acc += v[k].x * v[k].x + v[k].y * v[k].y;

    #pragma unroll
    for (int o = 16; o; o >>= 1) acc += __shfl_xor_sync(0xffffffffu, acc, o);
    if ((t & 31) == 0) red[t >> 5] = acc;
    __syncthreads();
    if (t == 0) {
        float s = 0.f;
        #pragma unroll
        for (int w = 0; w < 8; ++w) s += red[w];
        out[b] = s;
    }
}

// ---------------------------------------------------------------------------
extern "C" void kernel_launch(void* const* d_in, const int* in_sizes, int n_in,
                              void* d_out, int out_size)
{
    const float* x  = (const float*)d_in[0];   // (1024, 2, 32, 32) -> (1024, 2048)
    const float* Wm = (const float*)d_in[1];   // (512, 2048)
    const float* bb = (const float*)d_in[2];   // (512,)
    const float* qp = (const float*)d_in[3];   // (2, 12, 3)
    float* out = (float*)d_out;                // (1024,)

    dim3 gemm_grid(512 / 128, 1024 / 128, SPLITK);   // (4, 8, 4) = 128 CTAs
    gemm_v2<<<gemm_grid, 256>>>(x, Wm);
    circuit_kernel<<<1024, 256>>>(x, bb, qp, out);
}

// round 5
// speedup vs baseline: 1.5235x; 1.0631x over previous
#include <cuda_runtime.h>
#include <math.h>

typedef unsigned long long u64;

#define SPLITK 4

// Split-K partial sums of x @ W^T (bias added in circuit kernel). No allocs.
__device__ float g_com4[SPLITK][1024 * 512];

// ---------------------------------------------------------------------------
// Packed fp32x2 helpers (PTX-only)
// ---------------------------------------------------------------------------
__device__ __forceinline__ u64 pk2(float lo, float hi) {
    u64 d; asm("mov.b64 %0, {%1, %2};" : "=l"(d) : "f"(lo), "f"(hi)); return d;
}
__device__ __forceinline__ u64 fma2(u64 a, u64 b, u64 c) {
    u64 d; asm("fma.rn.f32x2 %0, %1, %2, %3;" : "=l"(d) : "l"(a), "l"(b), "l"(c)); return d;
}
__device__ __forceinline__ u64 mul2(u64 a, u64 b) {
    u64 d; asm("mul.rn.f32x2 %0, %1, %2;" : "=l"(d) : "l"(a), "l"(b)); return d;
}
__device__ __forceinline__ u64 add2(u64 a, u64 b) {
    u64 d; asm("add.rn.f32x2 %0, %1, %2;" : "=l"(d) : "l"(a), "l"(b)); return d;
}
__device__ __forceinline__ void unpk2(float& lo, float& hi, u64 d) {
    asm("mov.b64 {%0, %1}, %2;" : "=f"(lo), "=f"(hi) : "l"(d));
}
// i * A  (complex):  (ax, ay) -> (-ay, ax)
__device__ __forceinline__ u64 crot(u64 a) {
    float lo, hi; unpk2(lo, hi, a);
    return pk2(-hi, lo);
}

// ---------------------------------------------------------------------------
// GEMM v2 (unchanged): split-K partials of x @ W^T, f32x2 accumulators.
// ---------------------------------------------------------------------------
__global__ __launch_bounds__(256)
void gemm_v2(const float* __restrict__ A, const float* __restrict__ Wm)
{
    __shared__ __align__(16) float As[2][16][132];
    __shared__ __align__(16) float Ws[2][16][132];

    const int tid = threadIdx.x;
    const int n0 = blockIdx.x * 128;
    const int m0 = blockIdx.y * 128;
    const int kb = blockIdx.z * 512;
    const int r  = tid >> 1;
    const int kh = (tid & 1) << 3;
    const int ty = tid >> 4;
    const int tx = tid & 15;

    const float* Ap = A  + (size_t)(m0 + r) * 2048 + kb + kh;
    const float* Wp = Wm + (size_t)(n0 + r) * 2048 + kb + kh;

    u64 acc[8][4];
    #pragma unroll
    for (int i = 0; i < 8; ++i)
        #pragma unroll
        for (int j = 0; j < 4; ++j) acc[i][j] = 0ull;

    float4 a0 = *(const float4*)Ap;
    float4 a1 = *(const float4*)(Ap + 4);
    float4 w0 = *(const float4*)Wp;
    float4 w1 = *(const float4*)(Wp + 4);

    #pragma unroll 1
    for (int it = 0; it < 32; ++it) {
        const int buf = it & 1;
        As[buf][kh + 0][r] = a0.x; As[buf][kh + 1][r] = a0.y;
        As[buf][kh + 2][r] = a0.z; As[buf][kh + 3][r] = a0.w;
        As[buf][kh + 4][r] = a1.x; As[buf][kh + 5][r] = a1.y;
        As[buf][kh + 6][r] = a1.z; As[buf][kh + 7][r] = a1.w;
        Ws[buf][kh + 0][r] = w0.x; Ws[buf][kh + 1][r] = w0.y;
        Ws[buf][kh + 2][r] = w0.z; Ws[buf][kh + 3][r] = w0.w;
        Ws[buf][kh + 4][r] = w1.x; Ws[buf][kh + 5][r] = w1.y;
        Ws[buf][kh + 6][r] = w1.z; Ws[buf][kh + 7][r] = w1.w;

        if (it + 1 < 32) {
            const float* Ap2 = Ap + (it + 1) * 16;
            const float* Wp2 = Wp + (it + 1) * 16;
            a0 = *(const float4*)Ap2; a1 = *(const float4*)(Ap2 + 4);
            w0 = *(const float4*)Wp2; w1 = *(const float4*)(Wp2 + 4);
        }
        __syncthreads();

        #pragma unroll
        for (int kk = 0; kk < 16; ++kk) {
            float4 af0 = *(const float4*)&As[buf][kk][ty << 3];
            float4 af1 = *(const float4*)&As[buf][kk][(ty << 3) + 4];
            ulonglong2 q0 = *(const ulonglong2*)&Ws[buf][kk][tx << 2];
            ulonglong2 q1 = *(const ulonglong2*)&Ws[buf][kk][64 + (tx << 2)];
            float av[8] = {af0.x, af0.y, af0.z, af0.w, af1.x, af1.y, af1.z, af1.w};
            #pragma unroll
            for (int i = 0; i < 8; ++i) {
                u64 ap = pk2(av[i], av[i]);
                acc[i][0] = fma2(ap, q0.x, acc[i][0]);
                acc[i][1] = fma2(ap, q0.y, acc[i][1]);
                acc[i][2] = fma2(ap, q1.x, acc[i][2]);
                acc[i][3] = fma2(ap, q1.y, acc[i][3]);
            }
        }
    }

    float* Cp = g_com4[blockIdx.z];
    #pragma unroll
    for (int i = 0; i < 8; ++i) {
        int row = m0 + (ty << 3) + i;
        *(ulonglong2*)&Cp[(size_t)row * 512 + n0 + (tx << 2)] =
            make_ulonglong2(acc[i][0], acc[i][1]);
        *(ulonglong2*)&Cp[(size_t)row * 512 + n0 + 64 + (tx << 2)] =
            make_ulonglong2(acc[i][2], acc[i][3]);
    }
}

// ---------------------------------------------------------------------------
// Quantum circuit: 1 CTA per batch row, state (4096 complex, AoS u64) in SMEM.
// Wire w <-> bit (11 - w).  Swizzle a(i) = i ^ ((i>>4) & 0xF).
// ---------------------------------------------------------------------------
__device__ __forceinline__ int swz(int i) { return i ^ ((i >> 4) & 0xF); }

// Packed complex 2x2 gate on pairs over local bit LB.
// cf = 8 pre-splatted u64 coefficients {c00x,c00y,c01x,c01y,c10x,c10y,c11x,c11y}.
template<int LB>
__device__ __forceinline__ void rot2(u64* v, const u64* __restrict__ cf)
{
    u64 c00x = cf[0], c00y = cf[1], c01x = cf[2], c01y = cf[3];
    u64 c10x = cf[4], c10y = cf[5], c11x = cf[6], c11y = cf[7];
    #pragma unroll
    for (int p = 0; p < 8; ++p) {
        int k0 = ((p >> LB) << (LB + 1)) | (p & ((1 << LB) - 1));
        int k1 = k0 | (1 << LB);
        u64 A = v[k0], B = v[k1];
        u64 Ar = crot(A), Br = crot(B);
        v[k0] = fma2(c00x, A, fma2(c00y, Ar, fma2(c01x, B, mul2(c01y, Br))));
        v[k1] = fma2(c10x, A, fma2(c10y, Ar, fma2(c11x, B, mul2(c11y, Br))));
    }
}

// Unscaled Hadamard butterfly (scale folded into final reduction).
template<int LB>
__device__ __forceinline__ void h2(u64* v, u64 neg1)
{
    #pragma unroll
    for (int p = 0; p < 8; ++p) {
        int k0 = ((p >> LB) << (LB + 1)) | (p & ((1 << LB) - 1));
        int k1 = k0 | (1 << LB);
        u64 A = v[k0], B = v[k1];
        v[k0] = add2(A, B);
        v[k1] = fma2(neg1, B, A);
    }
}

// Net gather index of the 12-CNOT chain with range R (GF(2)-linear).
template<int R>
__device__ __forceinline__ int cnotG(int i)
{
    #pragma unroll
    for (int w = 11; w >= 0; --w) {
        int pc = 11 - w;
        int pt = 11 - ((w + R) % 12);
        i ^= ((i >> pc) & 1) << pt;
    }
    return i;
}

__global__ __launch_bounds__(256, 2)
void circuit_kernel(const float* __restrict__ x,    // (1024, 2048) img angles
                    const float* __restrict__ bias, // (512,)
                    const float* __restrict__ qp,   // (2, 12, 3)
                    float* __restrict__ out)        // (1024,)
{
    __shared__ u64 st[4096];             // 32 KB state (packed complex)
    __shared__ u64 cf2[2][12][8];        // pre-splatted gate coefficients
    __shared__ float red[8];

    const int t = threadIdx.x;
    const int b = blockIdx.x;
    const float* img = x + (size_t)b * 2048;
    const size_t crow = (size_t)b * 512;

    // --- Rot matrices, splatted: Rot = RZ(omega) RY(theta) RZ(phi) ---
    if (t < 24) {
        int l = t / 12, w = t % 12;
        float phi = qp[(l * 12 + w) * 3 + 0];
        float th  = qp[(l * 12 + w) * 3 + 1];
        float om  = qp[(l * 12 + w) * 3 + 2];
        float sh, ch;  sincosf(0.5f * th, &sh, &ch);
        float sa, ca;  sincosf(0.5f * (phi + om), &sa, &ca);
        float sb, cb;  sincosf(0.5f * (phi - om), &sb, &cb);
        u64* c = cf2[l][w];
        c[0] = pk2( ch * ca,  ch * ca);   // m00.x
        c[1] = pk2(-ch * sa, -ch * sa);   // m00.y
        c[2] = pk2(-sh * cb, -sh * cb);   // m01.x
        c[3] = pk2(-sh * sb, -sh * sb);   // m01.y
        c[4] = pk2( sh * cb,  sh * cb);   // m10.x
        c[5] = pk2(-sh * sb, -sh * sb);   // m10.y
        c[6] = pk2( ch * ca,  ch * ca);   // m11.x
        c[7] = pk2( ch * sa,  ch * sa);   // m11.y
    }
    __syncthreads();

    const u64 neg1 = pk2(-1.f, -1.f);
    u64 v[16];

    // ===== Pass 1 (nibble A: bits 0-3 local) : analytic FRQI(com), L0 Rots 11..8
    #pragma unroll
    for (int k = 0; k < 16; ++k) {
        int i = (t << 4) | k;
        if (i & 3) {
            v[k] = 0ull;
        } else {
            int j = (i >> 2) & 511;
            int aidx = __brev((unsigned)j) >> 23;
            float comv = bias[aidx]
                       + g_com4[0][crow + aidx] + g_com4[1][crow + aidx]
                       + g_com4[2][crow + aidx] + g_com4[3][crow + aidx];
            float sn, cs; __sincosf(0.5f * comv, &sn, &cs);
            float amp = ((i >> 11) & 1) ? sn : cs;
            v[k] = pk2(amp * 0.04419417382415922f, 0.f);  // 1/sqrt(512)
        }
    }
    rot2<0>(v, cf2[0][11]); rot2<1>(v, cf2[0][10]);
    rot2<2>(v, cf2[0][9]);  rot2<3>(v, cf2[0][8]);
    #pragma unroll
    for (int k = 0; k < 16; ++k) st[swz((t << 4) | k)] = v[k];
    __syncthreads();

    // ===== Pass 2 (B: bits 4-7) : L0 Rots 7..4
    #pragma unroll
    for (int k = 0; k < 16; ++k) v[k] = st[swz(((t >> 4) << 8) | (k << 4) | (t & 15))];
    rot2<0>(v, cf2[0][7]); rot2<1>(v, cf2[0][6]);
    rot2<2>(v, cf2[0][5]); rot2<3>(v, cf2[0][4]);
    #pragma unroll
    for (int k = 0; k < 16; ++k) st[swz(((t >> 4) << 8) | (k << 4) | (t & 15))] = v[k];
    __syncthreads();

    // ===== Pass 3 (C: bits 8-11) : L0 Rots 3..0
    #pragma unroll
    for (int k = 0; k < 16; ++k) v[k] = st[swz((k << 8) | t)];
    rot2<0>(v, cf2[0][3]); rot2<1>(v, cf2[0][2]);
    rot2<2>(v, cf2[0][1]); rot2<3>(v, cf2[0][0]);
    #pragma unroll
    for (int k = 0; k < 16; ++k) st[swz((k << 8) | t)] = v[k];
    __syncthreads();

    // ===== Pass 4 (A) : CNOT r=1 folded gather, L1 Rots 11..8
    {
        int base = cnotG<1>(t << 4);
        int m0 = cnotG<1>(1), m1 = cnotG<1>(2), m2 = cnotG<1>(4), m3 = cnotG<1>(8);
        #pragma unroll
        for (int k = 0; k < 16; ++k) {
            int gi = base ^ ((k & 1) ? m0 : 0) ^ ((k & 2) ? m1 : 0)
                          ^ ((k & 4) ? m2 : 0) ^ ((k & 8) ? m3 : 0);
            v[k] = st[swz(gi)];
        }
    }
    __syncthreads();
    rot2<0>(v, cf2[1][11]); rot2<1>(v, cf2[1][10]);
    rot2<2>(v, cf2[1][9]);  rot2<3>(v, cf2[1][8]);
    #pragma unroll
    for (int k = 0; k < 16; ++k) st[swz((t << 4) | k)] = v[k];
    __syncthreads();

    // ===== Pass 5 (B) : L1 Rots 7..4
    #pragma unroll
    for (int k = 0; k < 16; ++k) v[k] = st[swz(((t >> 4) << 8) | (k << 4) | (t & 15))];
    rot2<0>(v, cf2[1][7]); rot2<1>(v, cf2[1][6]);
    rot2<2>(v, cf2[1][5]); rot2<3>(v, cf2[1][4]);
    #pragma unroll
    for (int k = 0; k < 16; ++k) st[swz(((t >> 4) << 8) | (k << 4) | (t & 15))] = v[k];
    __syncthreads();

    // ===== Pass 6 (C) : L1 Rots 3..0
    #pragma unroll
    for (int k = 0; k < 16; ++k) v[k] = st[swz((k << 8) | t)];
    rot2<0>(v, cf2[1][3]); rot2<1>(v, cf2[1][2]);
    rot2<2>(v, cf2[1][1]); rot2<3>(v, cf2[1][0]);
    #pragma unroll
    for (int k = 0; k < 16; ++k) st[swz((k << 8) | t)] = v[k];
    __syncthreads();

    // ===== Pass 7 (A) : CNOT r=2 folded gather, H on bits 0-3 (unscaled)
    {
        int base = cnotG<2>(t << 4);
        int m0 = cnotG<2>(1), m1 = cnotG<2>(2), m2 = cnotG<2>(4), m3 = cnotG<2>(8);
        #pragma unroll
        for (int k = 0; k < 16; ++k) {
            int gi = base ^ ((k & 1) ? m0 : 0) ^ ((k & 2) ? m1 : 0)
                          ^ ((k & 4) ? m2 : 0) ^ ((k & 8) ? m3 : 0);
            v[k] = st[swz(gi)];
        }
    }
    __syncthreads();
    h2<0>(v, neg1); h2<1>(v, neg1); h2<2>(v, neg1); h2<3>(v, neg1);
    #pragma unroll
    for (int k = 0; k < 16; ++k) st[swz((t << 4) | k)] = v[k];
    __syncthreads();

    // ===== Pass 8 (B) : H on bits 4-7 (unscaled)
    #pragma unroll
    for (int k = 0; k < 16; ++k) v[k] = st[swz(((t >> 4) << 8) | (k << 4) | (t & 15))];
    h2<0>(v, neg1); h2<1>(v, neg1); h2<2>(v, neg1); h2<3>(v, neg1);
    #pragma unroll
    for (int k = 0; k < 16; ++k) st[swz(((t >> 4) << 8) | (k << 4) | (t & 15))] = v[k];
    __syncthreads();

    // ===== Pass 9 (C) : H bits 8-10 (unscaled), UC-RY(img) on wire 0, measure
    #pragma unroll
    for (int k = 0; k < 16; ++k) v[k] = st[swz((k << 8) | t)];
    h2<0>(v, neg1); h2<1>(v, neg1); h2<2>(v, neg1);

    #pragma unroll
    for (int k0 = 0; k0 < 8; ++k0) {
        int i0 = (k0 << 8) | t;
        int aidx = __brev((unsigned)i0) >> 21;
        float sn, cs; __sincosf(0.5f * img[aidx], &sn, &cs);
        u64 A = v[k0], B = v[k0 + 8];
        u64 cs2 = pk2(cs, cs), sn2 = pk2(sn, sn), sn2n = pk2(-sn, -sn);
        v[k0]     = fma2(cs2, A, mul2(sn2n, B));
        v[k0 + 8] = fma2(sn2, A, mul2(cs2, B));
    }

    u64 accN = 0ull, accP = 0ull;
    #pragma unroll
    for (int k = 0; k < 8; ++k)  accN = fma2(v[k], v[k], accN);
    #pragma unroll
    for (int k = 8; k < 16; ++k) accP = fma2(v[k], v[k], accP);
    float pl, ph, nl, nh;
    unpk2(pl, ph, accP); unpk2(nl, nh, accN);
    float acc = (pl + ph) - (nl + nh);

    #pragma unroll
    for (int o = 16; o; o >>= 1) acc += __shfl_xor_sync(0xffffffffu, acc, o);
    if ((t & 31) == 0) red[t >> 5] = acc;
    __syncthreads();
    if (t == 0) {
        float s = 0.f;
        #pragma unroll
        for (int w = 0; w < 8; ++w) s += red[w];
        out[b] = s * (1.0f / 2048.0f);   // fold (1/sqrt(2))^11 amplitude scale (squared)
    }
}

// ---------------------------------------------------------------------------
extern "C" void kernel_launch(void* const* d_in, const int* in_sizes, int n_in,
                              void* d_out, int out_size)
{
    const float* x  = (const float*)d_in[0];   // (1024, 2, 32, 32) -> (1024, 2048)
    const float* Wm = (const float*)d_in[1];   // (512, 2048)
    const float* bb = (const float*)d_in[2];   // (512,)
    const float* qp = (const float*)d_in[3];   // (2, 12, 3)
    float* out = (float*)d_out;                // (1024,)

    dim3 gemm_grid(512 / 128, 1024 / 128, SPLITK);   // 128 CTAs
    gemm_v2<<<gemm_grid, 256>>>(x, Wm);
    circuit_kernel<<<1024, 256>>>(x, bb, qp, out);
}